// round 7
// baseline (speedup 1.0000x reference)
#include <cuda_runtime.h>
#include <cuda_bf16.h>
#include <cstdint>

// CostVolumn: out[b, dy*9+dx, y, x] = leaky( mean_c( c1[b,c,y,x] * warped_pad[b,c,y+dy-4, x+dx-4] ) )
// f32x2-packed FMA, 8-px x-tiles, cp.async double buffer, conflict-free smem strides.

namespace {
constexpr int B_ = 8;
constexpr int C_ = 192;
constexpr int H_ = 128;
constexpr int W_ = 160;
constexpr int SR = 4;
constexpr int MO = 9;
constexpr int TH = 8;
constexpr int TW = 32;
constexpr int CC = 16;
constexpr int NCH = C_ / CC;            // 12
constexpr int HALO_H = TH + 2 * SR;     // 16
constexpr int HALO_W = TW + 2 * SR;     // 40
constexpr int NTHREADS = 8 * 4 * 9;     // 288
constexpr int HW = H_ * W_;

constexpr int SWROW = 44;   // w row stride (40 used + 4 pad); 44 mod 32 = 12 -> conflict-free
constexpr int SAROW = 36;   // a row stride (32 used + 4 pad); 36 mod 32 = 4  -> conflict-free

constexpr int SW_ELEMS = CC * HALO_H * SWROW;   // 11264 floats
constexpr int SA_ELEMS = CC * TH * SAROW;       // 4608 floats
constexpr int STAGE = SW_ELEMS + SA_ELEMS;      // 15872 floats
constexpr int SMEM_BYTES = 2 * STAGE * 4;       // 126976 B

// 16B staging units
constexpr int UW = CC * HALO_H * (HALO_W / 4);  // 2560
constexpr int UC = CC * TH * (TW / 4);          // 1024
constexpr int UTOT = UW + UC;                   // 3584
constexpr int SLOTS = (UTOT + NTHREADS - 1) / NTHREADS;  // 13
}

using ull = unsigned long long;

__device__ __forceinline__ ull pk(float lo, float hi) {
    ull r;
    asm("mov.b64 %0, {%1, %2};" : "=l"(r) : "f"(lo), "f"(hi));
    return r;
}
__device__ __forceinline__ void upk(ull v, float& lo, float& hi) {
    asm("mov.b64 {%0, %1}, %2;" : "=f"(lo), "=f"(hi) : "l"(v));
}
__device__ __forceinline__ void fma2(ull& d, ull a, ull b) {
    asm("fma.rn.f32x2 %0, %1, %2, %0;" : "+l"(d) : "l"(a), "l"(b));
}

__global__ __launch_bounds__(NTHREADS, 1)
void costvol_kernel(const float* __restrict__ c1,
                    const float* __restrict__ warped,
                    const float* __restrict__ alpha,
                    float* __restrict__ out) {
    extern __shared__ float smem[];

    const int ly = threadIdx.x;   // tile row 0..7 (fastest -> conflict-free phases)
    const int q  = threadIdx.y;   // x-oct 0..3 (x = 8q..8q+7)
    const int dz = threadIdx.z;   // dy 0..8
    const int tid = ly + 8 * (q + 4 * dz);

    const int x0 = blockIdx.x * TW;
    const int y0 = blockIdx.y * TH;
    const int b  = blockIdx.z;

    const float* __restrict__ c1b = c1 + (size_t)b * C_ * HW;
    const float* __restrict__ wb  = warped + (size_t)b * C_ * HW;

    // ---- per-thread staging slots (geometry fixed across chunks) ----
    uint32_t soff[SLOTS];
    int32_t  goff[SLOTS];
    bool     valid[SLOTS];
    bool     isw[SLOTS];
#pragma unroll
    for (int s = 0; s < SLOTS; s++) {
        valid[s] = false; isw[s] = false; soff[s] = 0; goff[s] = 0;
        int i = tid + NTHREADS * s;
        if (i < UW) {
            int cc = i / (HALO_H * 10);
            int rem = i % (HALO_H * 10);
            int hy = rem / 10;
            int seg = rem % 10;
            int gy = y0 + hy - SR;
            int gx = x0 - SR + seg * 4;
            isw[s] = true;
            soff[s] = (uint32_t)(cc * (HALO_H * SWROW) + hy * SWROW + seg * 4) * 4u;
            goff[s] = cc * HW + gy * W_ + gx;
            valid[s] = (gy >= 0) && (gy < H_) && (gx >= 0) && (gx + 4 <= W_);
        } else if (i < UTOT) {
            int j = i - UW;
            int cc = j / (TH * 8);
            int rem = j % (TH * 8);
            int yy = rem / 8;
            int seg = rem % 8;
            soff[s] = (uint32_t)(SW_ELEMS + cc * (TH * SAROW) + yy * SAROW + seg * 4) * 4u;
            goff[s] = cc * HW + (y0 + yy) * W_ + (x0 + seg * 4);
            valid[s] = true;
        }
    }

    // ---- zero warped regions once (OOB halo padding persists across stages) ----
    for (int i = tid; i < SW_ELEMS; i += NTHREADS) {
        smem[i] = 0.f;
        smem[STAGE + i] = 0.f;
    }
    __syncthreads();

    const uint32_t smem_u32 = (uint32_t)__cvta_generic_to_shared(smem);

    auto issue_stage = [&](int k) {
        const uint32_t sbase = smem_u32 + (uint32_t)((k & 1) * STAGE) * 4u;
        const size_t coff = (size_t)(k * CC) * HW;
#pragma unroll
        for (int s = 0; s < SLOTS; s++) {
            if (valid[s]) {
                const float* g = (isw[s] ? wb : c1b) + coff + goff[s];
                uint32_t sa = sbase + soff[s];
                asm volatile("cp.async.cg.shared.global [%0], [%1], 16;"
                             :: "r"(sa), "l"(g) : "memory");
            }
        }
        asm volatile("cp.async.commit_group;" ::: "memory");
    };

    issue_stage(0);
    issue_stage(1);

    // accumulators (f32x2 packed):
    // even dx (0,2,4,6,8): pairs over xi (0,1)(2,3)(4,5)(6,7)
    // odd  dx (1,3,5,7):   scalar xi=0, pairs (1,2)(3,4)(5,6), scalar xi=7
    ull   accE[5][4];
    ull   accO[4][3];
    float acc0[4], acc7[4];
#pragma unroll
    for (int d = 0; d < 5; d++)
#pragma unroll
        for (int m = 0; m < 4; m++) accE[d][m] = 0ull;
#pragma unroll
    for (int o = 0; o < 4; o++) {
#pragma unroll
        for (int m = 0; m < 3; m++) accO[o][m] = 0ull;
        acc0[o] = 0.f; acc7[o] = 0.f;
    }

    for (int k = 0; k < NCH; k++) {
        if (k + 1 < NCH) {
            asm volatile("cp.async.wait_group 1;" ::: "memory");
        } else {
            asm volatile("cp.async.wait_group 0;" ::: "memory");
        }
        __syncthreads();

        const float* ws = smem + (k & 1) * STAGE;
        const float* as = ws + SW_ELEMS;

#pragma unroll
        for (int cc = 0; cc < CC; cc++) {
            const float* arow = as + cc * (TH * SAROW) + ly * SAROW + 8 * q;
            float4 aA = *reinterpret_cast<const float4*>(arow);
            float4 aB = *reinterpret_cast<const float4*>(arow + 4);

            const float* wrow = ws + cc * (HALO_H * SWROW) + (ly + dz) * SWROW + 8 * q;
            float4 w0 = *reinterpret_cast<const float4*>(wrow);
            float4 w1 = *reinterpret_cast<const float4*>(wrow + 4);
            float4 w2 = *reinterpret_cast<const float4*>(wrow + 8);
            float4 w3 = *reinterpret_cast<const float4*>(wrow + 12);

            // even w pairs P[j] = (w[2j], w[2j+1]) straight from the float4s
            ull P[8];
            P[0] = pk(w0.x, w0.y); P[1] = pk(w0.z, w0.w);
            P[2] = pk(w1.x, w1.y); P[3] = pk(w1.z, w1.w);
            P[4] = pk(w2.x, w2.y); P[5] = pk(w2.z, w2.w);
            P[6] = pk(w3.x, w3.y); P[7] = pk(w3.z, w3.w);

            // a even pairs
            ull Ae[4] = {pk(aA.x, aA.y), pk(aA.z, aA.w), pk(aB.x, aB.y), pk(aB.z, aB.w)};
            // a odd-shifted pairs (a1,a2)(a3,a4)(a5,a6)
            ull Ao[3] = {pk(aA.y, aA.z), pk(aA.w, aB.x), pk(aB.y, aB.z)};

            // even dx = 2d
#pragma unroll
            for (int d = 0; d < 5; d++)
#pragma unroll
                for (int m = 0; m < 4; m++)
                    fma2(accE[d][m], Ae[m], P[d + m]);

            // odd dx = 2o+1
#pragma unroll
            for (int o = 0; o < 4; o++) {
                float plo, phi;
                upk(P[o], plo, phi);          // phi = w[2o+1] = w[dx]
                acc0[o] = fmaf(aA.x, phi, acc0[o]);
#pragma unroll
                for (int m = 0; m < 3; m++)
                    fma2(accO[o][m], Ao[m], P[o + 1 + m]);
                float qlo, qhi;
                upk(P[o + 4], qlo, qhi);      // qlo = w[2o+8] = w[dx+7]
                acc7[o] = fmaf(aB.w, qlo, acc7[o]);
            }
        }

        __syncthreads();
        if (k + 2 < NCH) issue_stage(k + 2);
    }

    // ---- epilogue: mean + leaky, 2x float4 stores per dx ----
    const float al = __ldg(alpha);
    const float inv = 1.0f / (float)C_;
    const int gy = y0 + ly;
    const int gxbase = x0 + q * 8;

    auto emit = [&](int dx, const float* v8) {
        int o = dz * MO + dx;
        float* dst = out + ((size_t)(b * 81 + o) * H_ + gy) * W_ + gxbase;
        float4 v;
        float t;
        t = v8[0] * inv; v.x = (t >= 0.f) ? t : al * t;
        t = v8[1] * inv; v.y = (t >= 0.f) ? t : al * t;
        t = v8[2] * inv; v.z = (t >= 0.f) ? t : al * t;
        t = v8[3] * inv; v.w = (t >= 0.f) ? t : al * t;
        *reinterpret_cast<float4*>(dst) = v;
        t = v8[4] * inv; v.x = (t >= 0.f) ? t : al * t;
        t = v8[5] * inv; v.y = (t >= 0.f) ? t : al * t;
        t = v8[6] * inv; v.z = (t >= 0.f) ? t : al * t;
        t = v8[7] * inv; v.w = (t >= 0.f) ? t : al * t;
        *reinterpret_cast<float4*>(dst + 4) = v;
    };

#pragma unroll
    for (int d = 0; d < 5; d++) {
        float v8[8];
        upk(accE[d][0], v8[0], v8[1]);
        upk(accE[d][1], v8[2], v8[3]);
        upk(accE[d][2], v8[4], v8[5]);
        upk(accE[d][3], v8[6], v8[7]);
        emit(2 * d, v8);
    }
#pragma unroll
    for (int o = 0; o < 4; o++) {
        float v8[8];
        v8[0] = acc0[o];
        upk(accO[o][0], v8[1], v8[2]);
        upk(accO[o][1], v8[3], v8[4]);
        upk(accO[o][2], v8[5], v8[6]);
        v8[7] = acc7[o];
        emit(2 * o + 1, v8);
    }
}

extern "C" void kernel_launch(void* const* d_in, const int* in_sizes, int n_in,
                              void* d_out, int out_size) {
    const float* c1     = (const float*)d_in[0];
    const float* warped = (const float*)d_in[1];
    const float* alpha  = (const float*)d_in[2];
    float* out = (float*)d_out;

    cudaFuncSetAttribute(costvol_kernel,
                         cudaFuncAttributeMaxDynamicSharedMemorySize, SMEM_BYTES);

    dim3 block(8, 4, 9);              // 288
    dim3 grid(W_ / TW, H_ / TH, B_);  // (5, 16, 8)
    costvol_kernel<<<grid, block, SMEM_BYTES>>>(c1, warped, alpha, out);
}

// round 9
// speedup vs baseline: 1.2645x; 1.2645x over previous
#include <cuda_runtime.h>
#include <cstdint>

// CostVolumn: out[b, dy*9+dx, y, x] = leaky( mean_c( c1[b,c,y,x] * warped_pad[b,c,y+dy-4, x+dx-4] ) )
// f32x2 with load-native pairing, 4-px x-tiles, 2 CTAs/SM, cp.async double buffer.

namespace {
constexpr int B_ = 8;
constexpr int C_ = 192;
constexpr int H_ = 128;
constexpr int W_ = 160;
constexpr int SR = 4;
constexpr int MO = 9;
constexpr int TH = 4;
constexpr int TW = 32;
constexpr int CC = 8;
constexpr int NCH = C_ / CC;            // 24
constexpr int HALO_H = TH + 2 * SR;     // 12
constexpr int HALO_W = TW + 2 * SR;     // 40
constexpr int NTHREADS = 8 * 4 * 9;     // 288
constexpr int HW = H_ * W_;

constexpr int SWROW = 44;   // w row stride, 16B-aligned rows
constexpr int SAROW = 36;   // a row stride, 16B-aligned rows

constexpr int SW_ELEMS = CC * HALO_H * SWROW;   // 4224 floats
constexpr int SA_ELEMS = CC * TH * SAROW;       // 1152 floats
constexpr int STAGE = SW_ELEMS + SA_ELEMS;      // 5376 floats
constexpr int SMEM_BYTES = 2 * STAGE * 4;       // 43008 B  (x2 CTAs = 86 KB/SM)

// 16B staging units
constexpr int UW = CC * HALO_H * (HALO_W / 4);  // 960
constexpr int UC = CC * TH * (TW / 4);          // 256
constexpr int UTOT = UW + UC;                   // 1216
constexpr int SLOTS = (UTOT + NTHREADS - 1) / NTHREADS;  // 5
}

using ull = unsigned long long;

__device__ __forceinline__ void fma2(ull& d, ull a, ull b) {
    asm("fma.rn.f32x2 %0, %1, %2, %0;" : "+l"(d) : "l"(a), "l"(b));
}
__device__ __forceinline__ void upk(ull v, float& lo, float& hi) {
    asm("mov.b64 {%0, %1}, %2;" : "=f"(lo), "=f"(hi) : "l"(v));
}
// (hi of p, lo of q) — odd-aligned pair from two even-aligned pairs
__device__ __forceinline__ ull mkodd(ull p, ull q) {
    ull r;
    asm("{\n\t"
        ".reg .b32 plo, phi, qlo, qhi;\n\t"
        "mov.b64 {plo, phi}, %1;\n\t"
        "mov.b64 {qlo, qhi}, %2;\n\t"
        "mov.b64 %0, {phi, qlo};\n\t"
        "}"
        : "=l"(r) : "l"(p), "l"(q));
    return r;
}

__global__ __launch_bounds__(NTHREADS, 2)
void costvol_kernel(const float* __restrict__ c1,
                    const float* __restrict__ warped,
                    const float* __restrict__ alpha,
                    float* __restrict__ out) {
    extern __shared__ float smem[];

    const int q  = threadIdx.x;   // x-quad 0..7 (x = 4q..4q+3)
    const int ly = threadIdx.y;   // tile row 0..3
    const int dz = threadIdx.z;   // dy 0..8 (one dz per warp)
    const int tid = q + 8 * (ly + 4 * dz);

    const int x0 = blockIdx.x * TW;
    const int y0 = blockIdx.y * TH;
    const int b  = blockIdx.z;

    const float* __restrict__ c1b = c1 + (size_t)b * C_ * HW;
    const float* __restrict__ wb  = warped + (size_t)b * C_ * HW;

    // ---- staging slots as advancing global pointers (lean register state) ----
    const float* gp[SLOTS];
    uint32_t soff[SLOTS];
#pragma unroll
    for (int s = 0; s < SLOTS; s++) {
        gp[s] = nullptr; soff[s] = 0;
        int i = tid + NTHREADS * s;
        if (i < UW) {
            int cc = i / (HALO_H * 10);
            int rem = i % (HALO_H * 10);
            int hy = rem / 10;
            int seg = rem % 10;
            int gy = y0 + hy - SR;
            int gx = x0 - SR + seg * 4;
            soff[s] = (uint32_t)(cc * (HALO_H * SWROW) + hy * SWROW + seg * 4) * 4u;
            if (gy >= 0 && gy < H_ && gx >= 0 && gx + 4 <= W_)
                gp[s] = wb + cc * HW + gy * W_ + gx;
        } else if (i < UTOT) {
            int j = i - UW;
            int cc = j / (TH * 8);
            int rem = j % (TH * 8);
            int yy = rem / 8;
            int seg = rem % 8;
            soff[s] = (uint32_t)(SW_ELEMS + cc * (TH * SAROW) + yy * SAROW + seg * 4) * 4u;
            gp[s] = c1b + cc * HW + (y0 + yy) * W_ + (x0 + seg * 4);
        }
    }

    // ---- zero warped regions once (OOB halo padding persists across stages) ----
    for (int i = tid; i < SW_ELEMS; i += NTHREADS) {
        smem[i] = 0.f;
        smem[STAGE + i] = 0.f;
    }
    __syncthreads();

    const uint32_t smem_u32 = (uint32_t)__cvta_generic_to_shared(smem);

    auto issue_stage = [&](int k) {
        const uint32_t sbase = smem_u32 + (uint32_t)((k & 1) * STAGE) * 4u;
#pragma unroll
        for (int s = 0; s < SLOTS; s++) {
            if (gp[s]) {
                uint32_t sa = sbase + soff[s];
                asm volatile("cp.async.cg.shared.global [%0], [%1], 16;"
                             :: "r"(sa), "l"(gp[s]) : "memory");
                gp[s] += CC * HW;
            }
        }
        asm volatile("cp.async.commit_group;" ::: "memory");
    };

    issue_stage(0);
    issue_stage(1);

    // accumulators: even dx=2d -> accE[d][m], odd dx=2o+1 -> accO[o][m]
    // lane pairs over x: m=0 -> (x0,x1), m=1 -> (x2,x3)
    ull accE[5][2], accO[4][2];
#pragma unroll
    for (int d = 0; d < 5; d++) { accE[d][0] = 0ull; accE[d][1] = 0ull; }
#pragma unroll
    for (int o = 0; o < 4; o++) { accO[o][0] = 0ull; accO[o][1] = 0ull; }

    for (int k = 0; k < NCH; k++) {
        if (k + 1 < NCH) {
            asm volatile("cp.async.wait_group 1;" ::: "memory");
        } else {
            asm volatile("cp.async.wait_group 0;" ::: "memory");
        }
        __syncthreads();

        const float* ws = smem + (k & 1) * STAGE;
        const float* as = ws + SW_ELEMS;

#pragma unroll
        for (int cc = 0; cc < CC; cc++) {
            // a: 4 floats -> 2 even pairs, straight from LDS.128
            ulonglong2 ua = *reinterpret_cast<const ulonglong2*>(
                as + cc * (TH * SAROW) + ly * SAROW + 4 * q);
            ull Ae[2] = {ua.x, ua.y};

            // w: 12 floats -> 6 even pairs, straight from 3x LDS.128
            const float* wrow = ws + cc * (HALO_H * SWROW) + (ly + dz) * SWROW + 4 * q;
            ulonglong2 u0 = *reinterpret_cast<const ulonglong2*>(wrow);
            ulonglong2 u1 = *reinterpret_cast<const ulonglong2*>(wrow + 4);
            ulonglong2 u2 = *reinterpret_cast<const ulonglong2*>(wrow + 8);
            ull P[6] = {u0.x, u0.y, u1.x, u1.y, u2.x, u2.y};

            // odd-aligned pairs for odd dx
            ull Po[5];
#pragma unroll
            for (int j = 0; j < 5; j++) Po[j] = mkodd(P[j], P[j + 1]);

            // even dx = 2d: (a_{2m}, a_{2m+1}) * (w_{2d+2m}, w_{2d+2m+1})
#pragma unroll
            for (int d = 0; d < 5; d++)
#pragma unroll
                for (int m = 0; m < 2; m++)
                    fma2(accE[d][m], Ae[m], P[d + m]);

            // odd dx = 2o+1: (a_{2m}, a_{2m+1}) * (w_{2o+1+2m}, w_{2o+2+2m})
#pragma unroll
            for (int o = 0; o < 4; o++)
#pragma unroll
                for (int m = 0; m < 2; m++)
                    fma2(accO[o][m], Ae[m], Po[o + m]);
        }

        __syncthreads();
        if (k + 2 < NCH) issue_stage(k + 2);
    }

    // ---- epilogue: mean + leaky, one float4 store per dx ----
    const float al = __ldg(alpha);
    const float inv = 1.0f / (float)C_;
    const int gy = y0 + ly;
    const int gxbase = x0 + q * 4;

    auto emit = [&](int dx, ull p0, ull p1) {
        int o = dz * MO + dx;
        float v0, v1, v2, v3;
        upk(p0, v0, v1);
        upk(p1, v2, v3);
        float4 v;
        float t;
        t = v0 * inv; v.x = (t >= 0.f) ? t : al * t;
        t = v1 * inv; v.y = (t >= 0.f) ? t : al * t;
        t = v2 * inv; v.z = (t >= 0.f) ? t : al * t;
        t = v3 * inv; v.w = (t >= 0.f) ? t : al * t;
        float* dst = out + ((size_t)(b * 81 + o) * H_ + gy) * W_ + gxbase;
        *reinterpret_cast<float4*>(dst) = v;
    };

#pragma unroll
    for (int d = 0; d < 5; d++) emit(2 * d, accE[d][0], accE[d][1]);
#pragma unroll
    for (int o = 0; o < 4; o++) emit(2 * o + 1, accO[o][0], accO[o][1]);
}

extern "C" void kernel_launch(void* const* d_in, const int* in_sizes, int n_in,
                              void* d_out, int out_size) {
    const float* c1     = (const float*)d_in[0];
    const float* warped = (const float*)d_in[1];
    const float* alpha  = (const float*)d_in[2];
    float* out = (float*)d_out;

    cudaFuncSetAttribute(costvol_kernel,
                         cudaFuncAttributeMaxDynamicSharedMemorySize, SMEM_BYTES);

    dim3 block(8, 4, 9);              // 288 threads, 2 CTAs/SM
    dim3 grid(W_ / TW, H_ / TH, B_);  // (5, 32, 8) = 1280 blocks
    costvol_kernel<<<grid, block, SMEM_BYTES>>>(c1, warped, alpha, out);
}

// round 13
// speedup vs baseline: 1.3487x; 1.0666x over previous
#include <cuda_runtime.h>
#include <cstdint>

// CostVolumn: out[b, dy*9+dx, y, x] = leaky( mean_c( c1[b,c,y,x] * warped_pad[b,c,y+dy-4, x+dx-4] ) )
// f32x2 load-native pairing, 3-stage cp.async ring (1 barrier/chunk), 2 CTAs/SM.

namespace {
constexpr int B_ = 8;
constexpr int C_ = 192;
constexpr int H_ = 128;
constexpr int W_ = 160;
constexpr int SR = 4;
constexpr int MO = 9;
constexpr int TH = 4;
constexpr int TW = 32;
constexpr int CC = 8;
constexpr int NCH = C_ / CC;            // 24
constexpr int HALO_H = TH + 2 * SR;     // 12
constexpr int HALO_W = TW + 2 * SR;     // 40
constexpr int NTHREADS = 8 * 4 * 9;     // 288
constexpr int HW = H_ * W_;

constexpr int SWROW = 44;   // w row stride; 44 mod 32 = 12 -> conflict-free phases
constexpr int SAROW = 36;   // a row stride; 36 mod 32 = 4  -> conflict-free

constexpr int SW_ELEMS = CC * HALO_H * SWROW;   // 4224 floats
constexpr int SA_ELEMS = CC * TH * SAROW;       // 1152 floats
constexpr int STAGE = SW_ELEMS + SA_ELEMS;      // 5376 floats
constexpr int NSTAGES = 3;
constexpr int SMEM_BYTES = NSTAGES * STAGE * 4; // 64512 B (x2 CTAs = 126 KB/SM)

// 16B staging units
constexpr int UW = CC * HALO_H * (HALO_W / 4);  // 960
constexpr int UC = CC * TH * (TW / 4);          // 256
constexpr int UTOT = UW + UC;                   // 1216
constexpr int SLOTS = (UTOT + NTHREADS - 1) / NTHREADS;  // 5
}

using ull = unsigned long long;

__device__ __forceinline__ void fma2(ull& d, ull a, ull b) {
    asm("fma.rn.f32x2 %0, %1, %2, %0;" : "+l"(d) : "l"(a), "l"(b));
}
__device__ __forceinline__ void upk(ull v, float& lo, float& hi) {
    asm("mov.b64 {%0, %1}, %2;" : "=f"(lo), "=f"(hi) : "l"(v));  // free: register aliasing
}
// (hi of p, lo of q) — builds a new even-aligned 64-bit pair (2 real MOVs)
__device__ __forceinline__ ull mkodd(ull p, ull q) {
    ull r;
    asm("{\n\t"
        ".reg .b32 plo, phi, qlo, qhi;\n\t"
        "mov.b64 {plo, phi}, %1;\n\t"
        "mov.b64 {qlo, qhi}, %2;\n\t"
        "mov.b64 %0, {phi, qlo};\n\t"
        "}"
        : "=l"(r) : "l"(p), "l"(q));
    return r;
}

__global__ __launch_bounds__(NTHREADS, 2)
void costvol_kernel(const float* __restrict__ c1,
                    const float* __restrict__ warped,
                    const float* __restrict__ alpha,
                    float* __restrict__ out) {
    extern __shared__ float smem[];

    const int q  = threadIdx.x;   // x-quad 0..7 (x = 4q..4q+3)
    const int ly = threadIdx.y;   // tile row 0..3
    const int dz = threadIdx.z;   // dy 0..8
    const int tid = q + 8 * (ly + 4 * dz);

    const int x0 = blockIdx.x * TW;
    const int y0 = blockIdx.y * TH;
    const int b  = blockIdx.z;

    const float* __restrict__ c1b = c1 + (size_t)b * C_ * HW;
    const float* __restrict__ wb  = warped + (size_t)b * C_ * HW;

    // ---- staging slots as advancing global pointers ----
    const float* gp[SLOTS];
    uint32_t soff[SLOTS];
#pragma unroll
    for (int s = 0; s < SLOTS; s++) {
        gp[s] = nullptr; soff[s] = 0;
        int i = tid + NTHREADS * s;
        if (i < UW) {
            int cc = i / (HALO_H * 10);
            int rem = i % (HALO_H * 10);
            int hy = rem / 10;
            int seg = rem % 10;
            int gy = y0 + hy - SR;
            int gx = x0 - SR + seg * 4;
            soff[s] = (uint32_t)(cc * (HALO_H * SWROW) + hy * SWROW + seg * 4) * 4u;
            if (gy >= 0 && gy < H_ && gx >= 0 && gx + 4 <= W_)
                gp[s] = wb + cc * HW + gy * W_ + gx;
        } else if (i < UTOT) {
            int j = i - UW;
            int cc = j / (TH * 8);
            int rem = j % (TH * 8);
            int yy = rem / 8;
            int seg = rem % 8;
            soff[s] = (uint32_t)(SW_ELEMS + cc * (TH * SAROW) + yy * SAROW + seg * 4) * 4u;
            gp[s] = c1b + cc * HW + (y0 + yy) * W_ + (x0 + seg * 4);
        }
    }

    // ---- zero warped regions once in all stages (OOB halo padding persists) ----
    for (int st = 0; st < NSTAGES; st++)
        for (int i = tid; i < SW_ELEMS; i += NTHREADS)
            smem[st * STAGE + i] = 0.f;
    __syncthreads();

    const uint32_t smem_u32 = (uint32_t)__cvta_generic_to_shared(smem);

    auto issue_stage = [&](int k) {
        const uint32_t sbase = smem_u32 + (uint32_t)((k % NSTAGES) * STAGE) * 4u;
#pragma unroll
        for (int s = 0; s < SLOTS; s++) {
            if (gp[s]) {
                uint32_t sa = sbase + soff[s];
                asm volatile("cp.async.cg.shared.global [%0], [%1], 16;"
                             :: "r"(sa), "l"(gp[s]) : "memory");
                gp[s] += CC * HW;
            }
        }
        asm volatile("cp.async.commit_group;" ::: "memory");
    };

    issue_stage(0);
    issue_stage(1);
    issue_stage(2);

    // accumulators:
    //  even dx=2d: accE[d][m], m: x-pair (x0,x1) / (x2,x3)
    //  odd  dx=2o+1: mid pair (x1,x2) in accO[o]; x0 in acc0[o]; x3 in acc3[o]
    ull accE[5][2], accO[4];
    float acc0[4], acc3[4];
#pragma unroll
    for (int d = 0; d < 5; d++) { accE[d][0] = 0ull; accE[d][1] = 0ull; }
#pragma unroll
    for (int o = 0; o < 4; o++) { accO[o] = 0ull; acc0[o] = 0.f; acc3[o] = 0.f; }

    for (int k = 0; k < NCH; k++) {
        if (k == 0) {
            asm volatile("cp.async.wait_group 2;" ::: "memory");
        } else if (k + 1 < NCH) {
            asm volatile("cp.async.wait_group 1;" ::: "memory");
        } else {
            asm volatile("cp.async.wait_group 0;" ::: "memory");
        }
        __syncthreads();   // stage k visible; all threads finished chunk k-1

        // buffer (k-1)%3 == (k+2)%3 is now free -> refill it
        if (k >= 1 && k + 2 < NCH) issue_stage(k + 2);

        const float* ws = smem + (k % NSTAGES) * STAGE;
        const float* as = ws + SW_ELEMS;

#pragma unroll
        for (int cc = 0; cc < CC; cc++) {
            // a: 4 floats -> 2 even pairs straight from LDS.128
            ulonglong2 ua = *reinterpret_cast<const ulonglong2*>(
                as + cc * (TH * SAROW) + ly * SAROW + 4 * q);
            ull Ae[2] = {ua.x, ua.y};
            float a0, a1, a2, a3;
            upk(Ae[0], a0, a1);
            upk(Ae[1], a2, a3);
            ull Ao = mkodd(Ae[0], Ae[1]);   // (a1,a2) — the only real repack

            // w: 12 floats -> 6 even pairs straight from 3x LDS.128
            const float* wrow = ws + cc * (HALO_H * SWROW) + (ly + dz) * SWROW + 4 * q;
            ulonglong2 u0 = *reinterpret_cast<const ulonglong2*>(wrow);
            ulonglong2 u1 = *reinterpret_cast<const ulonglong2*>(wrow + 4);
            ulonglong2 u2 = *reinterpret_cast<const ulonglong2*>(wrow + 8);
            ull P[6] = {u0.x, u0.y, u1.x, u1.y, u2.x, u2.y};

            // even dx = 2d
#pragma unroll
            for (int d = 0; d < 5; d++)
#pragma unroll
                for (int m = 0; m < 2; m++)
                    fma2(accE[d][m], Ae[m], P[d + m]);

            // odd dx = 2o+1
#pragma unroll
            for (int o = 0; o < 4; o++) {
                fma2(accO[o], Ao, P[o + 1]);          // x1,x2
                float wlo, whi;
                upk(P[o], wlo, whi);                  // whi = w[2o+1] = w[dx]
                acc0[o] = fmaf(a0, whi, acc0[o]);     // x0
                upk(P[o + 2], wlo, whi);              // wlo = w[2o+4] = w[dx+3]
                acc3[o] = fmaf(a3, wlo, acc3[o]);     // x3
            }
        }
    }

    // ---- epilogue: mean + leaky, one float4 store per dx ----
    const float al = __ldg(alpha);
    const float inv = 1.0f / (float)C_;
    const int gy = y0 + ly;
    const int gxbase = x0 + q * 4;

    auto emit = [&](int dx, float v0, float v1, float v2, float v3) {
        int o = dz * MO + dx;
        float4 v;
        float t;
        t = v0 * inv; v.x = (t >= 0.f) ? t : al * t;
        t = v1 * inv; v.y = (t >= 0.f) ? t : al * t;
        t = v2 * inv; v.z = (t >= 0.f) ? t : al * t;
        t = v3 * inv; v.w = (t >= 0.f) ? t : al * t;
        float* dst = out + ((size_t)(b * 81 + o) * H_ + gy) * W_ + gxbase;
        *reinterpret_cast<float4*>(dst) = v;
    };

#pragma unroll
    for (int d = 0; d < 5; d++) {
        float v0, v1, v2, v3;
        upk(accE[d][0], v0, v1);
        upk(accE[d][1], v2, v3);
        emit(2 * d, v0, v1, v2, v3);
    }
#pragma unroll
    for (int o = 0; o < 4; o++) {
        float m1, m2;
        upk(accO[o], m1, m2);
        emit(2 * o + 1, acc0[o], m1, m2, acc3[o]);
    }
}

extern "C" void kernel_launch(void* const* d_in, const int* in_sizes, int n_in,
                              void* d_out, int out_size) {
    const float* c1     = (const float*)d_in[0];
    const float* warped = (const float*)d_in[1];
    const float* alpha  = (const float*)d_in[2];
    float* out = (float*)d_out;

    cudaFuncSetAttribute(costvol_kernel,
                         cudaFuncAttributeMaxDynamicSharedMemorySize, SMEM_BYTES);

    dim3 block(8, 4, 9);              // 288 threads, 2 CTAs/SM
    dim3 grid(W_ / TW, H_ / TH, B_);  // (5, 32, 8) = 1280 blocks
    costvol_kernel<<<grid, block, SMEM_BYTES>>>(c1, warped, alpha, out);
}